// round 5
// baseline (speedup 1.0000x reference)
#include <cuda_runtime.h>
#include <cstdint>

// Problem constants (from reference setup_inputs)
#define Bc    4
#define Nc    16384
#define Kc    27
#define BNc   (Bc * Nc)            // 65536
#define Tc    (BNc * Kc)           // 1769472
#define BASEc 70
#define BASE3 343000               // 70^3
#define TABLE_SIZE (Bc * BASE3)    // 1372000
#define SHIFTc 3

// Scan config: 256 threads * 8 items = 2048 per tile; Tc/2048 = 864 exactly.
#define SCAN_BLOCK 256
#define SCAN_ITEMS 8
#define SCAN_TILE  (SCAN_BLOCK * SCAN_ITEMS)  // 2048 = 1<<11
#define NTILES     (Tc / SCAN_TILE)           // 864

// Scratch (allocation-free rule: __device__ globals)
__device__ int g_table[TABLE_SIZE];   // first-occurrence t per key (INT_MAX = empty)
__device__ int g_keybase[BNc];        // encoded key of the center voxel per (b,n)
__device__ int g_scan[Tc];            // intra-tile exclusive scan of first-occurrence flags
__device__ int g_bsum[NTILES];        // per-tile flag totals
__device__ int g_bpre[NTILES];        // exclusive scan of tile totals

__device__ __forceinline__ int off_delta(int k) {
    int ox = k / 9 - 1;
    int oy = (k / 3) % 3 - 1;
    int oz = k % 3 - 1;
    return ox * (BASEc * BASEc) + oy * BASEc + oz;
}

// Zero the ENTIRE output buffer first (covers any padding past 6T+1).
__global__ void k_zero(float* __restrict__ out, long long out_size) {
    long long i = (long long)blockIdx.x * blockDim.x + threadIdx.x;
    long long stride = (long long)gridDim.x * blockDim.x;
    for (; i < out_size; i += stride) out[i] = 0.0f;
}

__global__ void k_init_table() {
    int i = blockIdx.x * blockDim.x + threadIdx.x;
    if (i < TABLE_SIZE) g_table[i] = 0x7fffffff;
}

// Data-independent outputs AS FLOAT: in_idx, rel_pos, out_key -1 padding.
__global__ void k_fill(float* __restrict__ out, long long out_size) {
    int i = blockIdx.x * blockDim.x + threadIdx.x;   // i in [0, 3*Tc)
    if (i >= 3 * Tc) return;
    long long p_okey = 3LL * Tc + i;
    if (p_okey < out_size) out[p_okey] = -1.0f;
    if (i < Tc) {
        int idx = i / Kc;
        if (i < out_size)    out[i] = (float)(idx & (Nc - 1));   // in_idx = n
        long long p_rp = 2LL * Tc + i;
        if (p_rp < out_size) out[p_rp] = (float)(i - idx * Kc);  // rel_pos = k
    }
}

__global__ void k_build(const int* __restrict__ coords,
                        const int* __restrict__ batch) {
    int idx = blockIdx.x * blockDim.x + threadIdx.x;   // idx = b*N + n
    if (idx >= BNc) return;
    int x = coords[idx * 3 + 0];
    int y = coords[idx * 3 + 1];
    int z = coords[idx * 3 + 2];
    int b = batch[idx];
    int kb = b * BASE3 + ((x + SHIFTc) * BASEc + (y + SHIFTc)) * BASEc + (z + SHIFTc);
    g_keybase[idx] = kb;
    int tb = idx * Kc;
#pragma unroll
    for (int k = 0; k < Kc; k++) {
        int key = kb + off_delta(k);
        if (key >= 0 && key < TABLE_SIZE)
            atomicMin(&g_table[key], tb + k);
    }
}

__global__ void k_flagscan() {
    __shared__ int warp_sums[SCAN_BLOCK / 32];
    int tile = blockIdx.x;
    int base = tile * SCAN_TILE + threadIdx.x * SCAN_ITEMS;

    int f[SCAN_ITEMS];
    int s = 0;
#pragma unroll
    for (int j = 0; j < SCAN_ITEMS; j++) {
        int t   = base + j;
        int idx = t / Kc;
        int k   = t - idx * Kc;
        int key = g_keybase[idx] + off_delta(k);
        int ft  = (key >= 0 && key < TABLE_SIZE) ? g_table[key] : -1;
        f[j] = (ft == t) ? 1 : 0;
        s += f[j];
    }

    int lane = threadIdx.x & 31, wid = threadIdx.x >> 5;
    int incl = s;
#pragma unroll
    for (int d = 1; d < 32; d <<= 1) {
        int v = __shfl_up_sync(0xffffffffu, incl, d);
        if (lane >= d) incl += v;
    }
    if (lane == 31) warp_sums[wid] = incl;
    __syncthreads();
    if (wid == 0) {
        int v = (lane < SCAN_BLOCK / 32) ? warp_sums[lane] : 0;
#pragma unroll
        for (int d = 1; d < 32; d <<= 1) {
            int u = __shfl_up_sync(0xffffffffu, v, d);
            if (lane >= d) v += u;
        }
        if (lane < SCAN_BLOCK / 32) warp_sums[lane] = v;
    }
    __syncthreads();

    int warp_off = (wid == 0) ? 0 : warp_sums[wid - 1];
    int run = warp_off + incl - s;
#pragma unroll
    for (int j = 0; j < SCAN_ITEMS; j++) {
        g_scan[base + j] = run;
        run += f[j];
    }
    if (threadIdx.x == SCAN_BLOCK - 1) g_bsum[tile] = warp_sums[SCAN_BLOCK / 32 - 1];
}

__global__ void k_scantiles(float* __restrict__ out, long long out_size) {
    __shared__ int sh[1024];
    int i = threadIdx.x;
    int v = (i < NTILES) ? g_bsum[i] : 0;
    sh[i] = v;
    __syncthreads();
#pragma unroll
    for (int d = 1; d < 1024; d <<= 1) {
        int u = (i >= d) ? sh[i - d] : 0;
        __syncthreads();
        sh[i] += u;
        __syncthreads();
    }
    if (i < NTILES) g_bpre[i] = sh[i] - v;                 // exclusive tile prefix
    if (i == NTILES - 1 && 6LL * Tc < out_size)
        out[6LL * Tc] = (float)sh[i];                      // num_out
}

__global__ void k_output(float* __restrict__ out, long long out_size) {
    int t = blockIdx.x * blockDim.x + threadIdx.x;
    if (t >= Tc) return;
    int idx = t / Kc;
    int k   = t - idx * Kc;
    int key = g_keybase[idx] + off_delta(k);
    int ft  = (key >= 0 && key < TABLE_SIZE) ? g_table[key] : t;
    if (ft < 0 || ft >= Tc) ft = t;
    int oi  = g_scan[ft] + g_bpre[ft >> 11];               // dense insertion-order index

    long long p_oi = 1LL * Tc + t;
    if (p_oi < out_size) out[p_oi] = (float)oi;            // out_idx

    if (ft == t) {                                         // first occurrence defines key #oi
        int rem = key % BASE3;
        if (rem < 0) rem += BASE3;
        int x = rem / (BASEc * BASEc) - SHIFTc;
        int y = (rem / BASEc) % BASEc - SHIFTc;
        int z = rem % BASEc - SHIFTc;
        long long p = 3LL * Tc + 3LL * oi;
        if (p + 2 < out_size) {
            out[p]     = (float)x;
            out[p + 1] = (float)y;
            out[p + 2] = (float)z;
        }
    }
}

extern "C" void kernel_launch(void* const* d_in, const int* in_sizes, int n_in,
                              void* d_out, int out_size) {
    // Identify inputs by SIZE: coordinates = [B,N,3] (3*BNc), batch = [B,N] (BNc).
    const int* coords = (const int*)d_in[0];
    const int* batch  = (const int*)d_in[n_in > 1 ? 1 : 0];
    for (int i = 0; i < n_in; i++) {
        if (in_sizes[i] == 3 * BNc) coords = (const int*)d_in[i];
        else if (in_sizes[i] == BNc) batch = (const int*)d_in[i];
    }
    float* out = (float*)d_out;     // __output__ dtype: float32
    long long osz = (long long)out_size;

    k_zero<<<2048, 256>>>(out, osz);
    k_init_table<<<(TABLE_SIZE + 255) / 256, 256>>>();
    k_fill<<<(3 * Tc + 255) / 256, 256>>>(out, osz);
    k_build<<<(BNc + 255) / 256, 256>>>(coords, batch);
    k_flagscan<<<NTILES, SCAN_BLOCK>>>();
    k_scantiles<<<1, 1024>>>(out, osz);
    k_output<<<(Tc + 255) / 256, 256>>>(out, osz);
}